// round 15
// baseline (speedup 1.0000x reference)
#include <cuda_runtime.h>
#include <cuda_bf16.h>
#include <math.h>
#include <stdint.h>

#define H_DIM 1024
#define E_NUM 8
#define I_DIM 4096
#define T_MAX 8192
#define SLOTS (2*T_MAX)

// ---------------- device scratch (no allocations allowed) -------------------
__device__ int      g_top_idx [T_MAX*2];
__device__ float    g_top_w   [T_MAX*2];
__device__ int      g_counts  [E_NUM];
__device__ int      g_off     [E_NUM];
__device__ int      g_tok     [E_NUM*T_MAX];
__device__ unsigned g_slotinfo[T_MAX*2];           // (e<<13)|pos per (token,k)
__device__ __nv_bfloat16 g_xhi [(size_t)T_MAX*H_DIM];
__device__ __nv_bfloat16 g_xlo [(size_t)T_MAX*H_DIM];
__device__ __nv_bfloat16 g_w1hi[(size_t)E_NUM*I_DIM*H_DIM]; // [E][I][H] K-major
__device__ __nv_bfloat16 g_w1lo[(size_t)E_NUM*I_DIM*H_DIM];
__device__ __nv_bfloat16 g_w3hi[(size_t)E_NUM*I_DIM*H_DIM];
__device__ __nv_bfloat16 g_w3lo[(size_t)E_NUM*I_DIM*H_DIM];
__device__ __nv_bfloat16 g_w2hi[(size_t)E_NUM*H_DIM*I_DIM]; // [E][H][I] K-major
__device__ __nv_bfloat16 g_w2lo[(size_t)E_NUM*H_DIM*I_DIM];
__device__ __nv_bfloat16 g_hhi [(size_t)(SLOTS+128)*I_DIM];
__device__ __nv_bfloat16 g_hlo [(size_t)(SLOTS+128)*I_DIM];
__device__ float         g_y   [(size_t)(SLOTS+128)*H_DIM]; // expert outputs

// ---------------- PTX helpers (baseline sm_80 features only) -----------------
__device__ __forceinline__ uint32_t smem_u32(const void* p){
    uint32_t a; asm("{ .reg .u64 t; cvta.to.shared.u64 t, %1; cvt.u32.u64 %0, t; }":"=r"(a):"l"(p)); return a;
}
__device__ __forceinline__ void cp16(uint32_t s, const void* g){
    uint64_t ga; asm("cvta.to.global.u64 %0, %1;" : "=l"(ga) : "l"(g));
    asm volatile("cp.async.cg.shared.global [%0], [%1], 16;" :: "r"(s), "l"(ga) : "memory");
}
#define CP_COMMIT() asm volatile("cp.async.commit_group;":::"memory")
#define CP_WAIT0()  asm volatile("cp.async.wait_group 0;":::"memory")

__device__ __forceinline__ void ldsm4(uint32_t* r, uint32_t a){
    asm volatile("ldmatrix.sync.aligned.m8n8.x4.shared.b16 {%0,%1,%2,%3}, [%4];"
        : "=r"(r[0]),"=r"(r[1]),"=r"(r[2]),"=r"(r[3]) : "r"(a));
}
__device__ __forceinline__ void mma_bf16(float* c, const uint32_t* a, const uint32_t* b){
    asm volatile("mma.sync.aligned.m16n8k16.row.col.f32.bf16.bf16.f32 "
        "{%0,%1,%2,%3}, {%4,%5,%6,%7}, {%8,%9}, {%0,%1,%2,%3};"
        : "+f"(c[0]),"+f"(c[1]),"+f"(c[2]),"+f"(c[3])
        : "r"(a[0]),"r"(a[1]),"r"(a[2]),"r"(a[3]), "r"(b[0]),"r"(b[1]));
}

// ---------------- 1) router + fused x hi/lo split -----------------------------
__global__ void router_kernel(const float* __restrict__ X, const float* __restrict__ GW, int T){
    int t=(blockIdx.x*blockDim.x+threadIdx.x)>>5, lane=threadIdx.x&31;
    if(t>=T) return;
    const float* xr=X+(size_t)t*H_DIM;
    float acc[E_NUM];
#pragma unroll
    for(int e=0;e<E_NUM;++e) acc[e]=0.f;
    for(int k=lane;k<H_DIM;k+=32){
        float xv=__ldg(xr+k);
        __nv_bfloat16 h=__float2bfloat16_rn(xv);           // fused split
        g_xhi[(size_t)t*H_DIM+k]=h;
        g_xlo[(size_t)t*H_DIM+k]=__float2bfloat16_rn(xv-__bfloat162float(h));
        float4 g0=*(const float4*)(GW+(size_t)k*E_NUM), g1=*(const float4*)(GW+(size_t)k*E_NUM+4);
        acc[0]+=xv*g0.x; acc[1]+=xv*g0.y; acc[2]+=xv*g0.z; acc[3]+=xv*g0.w;
        acc[4]+=xv*g1.x; acc[5]+=xv*g1.y; acc[6]+=xv*g1.z; acc[7]+=xv*g1.w;
    }
#pragma unroll
    for(int o=16;o>0;o>>=1)
#pragma unroll
        for(int e=0;e<E_NUM;++e) acc[e]+=__shfl_xor_sync(0xffffffffu,acc[e],o);
    if(lane==0){
        int i1=0;
#pragma unroll
        for(int e=1;e<E_NUM;++e) if(acc[e]>acc[i1]) i1=e;
        int i2=(i1==0)?1:0;
#pragma unroll
        for(int e=0;e<E_NUM;++e) if(e!=i1&&acc[e]>acc[i2]) i2=e;
        float d=expf(acc[i2]-acc[i1]);
        g_top_idx[2*t]=i1;   g_top_w[2*t]=1.f/(1.f+d);
        g_top_idx[2*t+1]=i2; g_top_w[2*t+1]=d/(1.f+d);
    }
}

// ---------------- 2) deterministic per-expert compaction ---------------------
__global__ void build_lists_kernel(int T){
    const int e=blockIdx.x, tid=threadIdx.x, lane=tid&31, wid=tid>>5;
    __shared__ int s_wsum[8]; __shared__ int s_base;
    if(tid==0) s_base=0;
    __syncthreads();
    for(int st=0;st<T;st+=256){
        int t=st+tid, flag=0, kidx=0;
        if(t<T){
            if(g_top_idx[2*t]==e){flag=1;kidx=0;}
            else if(g_top_idx[2*t+1]==e){flag=1;kidx=1;}
        }
        unsigned m=__ballot_sync(0xffffffffu,flag);
        if(lane==0) s_wsum[wid]=__popc(m);
        __syncthreads();
        int off=s_base;
        for(int i=0;i<wid;++i) off+=s_wsum[i];
        int pos=off+__popc(m&((1u<<lane)-1u));
        if(flag){
            g_tok[e*T_MAX+pos]=t;
            g_slotinfo[2*t+kidx]=((unsigned)e<<13)|(unsigned)pos;
        }
        __syncthreads();
        if(tid==0){ int tt=0;
#pragma unroll
            for(int i=0;i<8;++i) tt+=s_wsum[i];
            s_base+=tt; }
        __syncthreads();
    }
    if(tid==0) g_counts[e]=s_base;
}

// ---------------- 3) all weight transposes+splits in ONE kernel --------------
// 1D grid: [0,16384) w1, [16384,32768) w3, [32768,49152) w2. Tile 64(R)x32(C).
__global__ void prep_kernel(const float* __restrict__ w1, const float* __restrict__ w3,
                            const float* __restrict__ w2){
    if(blockIdx.x==0 && threadIdx.x==0 && threadIdx.y==0){
        int s=0;
#pragma unroll
        for(int e=0;e<E_NUM;++e){ g_off[e]=s; s+=g_counts[e]; }
    }
    int bid=blockIdx.x;
    const float* src; __nv_bfloat16 *dhi,*dlo; int R,C,bx,by,e;
    if(bid<32768){
        bool is1=bid<16384; int b=is1?bid:bid-16384;
        e=b>>11; b&=2047; bx=b&127; by=b>>7;          // C=I:128 x, R=H:16 y
        R=H_DIM; C=I_DIM;
        src=(is1?w1:w3)+(size_t)e*R*C;
        dhi=(is1?g_w1hi:g_w3hi)+(size_t)e*R*C; dlo=(is1?g_w1lo:g_w3lo)+(size_t)e*R*C;
    } else {
        int b=bid-32768; e=b>>11; b&=2047; bx=b&31; by=b>>5;  // C=H:32 x, R=I:64 y
        R=I_DIM; C=H_DIM;
        src=w2+(size_t)e*R*C;
        dhi=g_w2hi+(size_t)e*R*C; dlo=g_w2lo+(size_t)e*R*C;
    }
    __shared__ float s[64][33];
    int r0=by*64, c0=bx*32, tx=threadIdx.x, ty=threadIdx.y;  // 32x8
#pragma unroll
    for(int i=ty;i<64;i+=8)
        s[i][tx]=src[(size_t)(r0+i)*C+c0+tx];
    __syncthreads();
#pragma unroll
    for(int i=ty;i<32;i+=8){
        float v0=s[2*tx][i], v1=s[2*tx+1][i];
        __nv_bfloat16 h0=__float2bfloat16_rn(v0), h1=__float2bfloat16_rn(v1);
        __nv_bfloat162 hv; hv.x=h0; hv.y=h1;
        __nv_bfloat162 lv;
        lv.x=__float2bfloat16_rn(v0-__bfloat162float(h0));
        lv.y=__float2bfloat16_rn(v1-__bfloat162float(h1));
        size_t o=(size_t)(c0+i)*R+r0+2*tx;
        *(__nv_bfloat162*)(dhi+o)=hv;
        *(__nv_bfloat162*)(dlo+o)=lv;
    }
}

// ---------------- 4) GEMM1 (mma.sync): h = silu(x@w1)*(x@w3) ------------------
#define ROWB 80
#define A1_OFF(st,t) (512   + ((st)*2+(t))*10240)
#define B1_OFF(st,t) (41472 + ((st)*4+(t))*5120)
#define G1_SMEM 82432

__global__ void __launch_bounds__(256,2) moe_gemm1_mma(){
    const int e=blockIdx.z, cnt=g_counts[e];
    const int m0=blockIdx.y*128; if(m0>=cnt) return;
    const int n0=blockIdx.x*64;
    const int tid=threadIdx.x, lane=tid&31, wid=tid>>5;
    const int wm=wid&3, wn=wid>>2;
    extern __shared__ char sm[];
    uint32_t sb=smem_u32(sm);
    int* s_tok=(int*)sm;
    if(tid<128){ int r=m0+tid; s_tok[tid]=g_tok[e*T_MAX+(r<cnt?r:cnt-1)]; }
    __syncthreads();

    const size_t ebase=(size_t)e*I_DIM*H_DIM;
    const __nv_bfloat16* bsrc[4]={ g_w1hi+ebase+(size_t)n0*H_DIM, g_w1lo+ebase+(size_t)n0*H_DIM,
                                   g_w3hi+ebase+(size_t)n0*H_DIM, g_w3lo+ebase+(size_t)n0*H_DIM };
    const int c8=(tid&3)*8, c16=(tid&3)*16, lrow=tid>>2;

    auto load_stage=[&](int k0,int st){
#pragma unroll
        for(int half=0; half<2; ++half){
            int row=lrow+half*64;
            size_t so=(size_t)s_tok[row]*H_DIM + k0 + c8;
            cp16(sb + A1_OFF(st,0) + row*ROWB + c16, g_xhi+so);
            cp16(sb + A1_OFF(st,1) + row*ROWB + c16, g_xlo+so);
        }
#pragma unroll
        for(int t=0;t<4;++t)
            cp16(sb + B1_OFF(st,t) + lrow*ROWB + c16, bsrc[t]+(size_t)lrow*H_DIM + k0 + c8);
        CP_COMMIT();
    };

    float acc1[2][4][4], acc3[2][4][4];
#pragma unroll
    for(int i=0;i<2;++i)
#pragma unroll
    for(int j=0;j<4;++j)
#pragma unroll
    for(int k=0;k<4;++k){ acc1[i][j][k]=0.f; acc3[i][j][k]=0.f; }

    load_stage(0,0);
    const uint32_t a_r=(uint32_t)(wm*32+(lane&15)), a_c=((lane>>4)&1)*16;
    const uint32_t b_row8=(uint32_t)((lane&7) + ((lane>>4)&1)*8);
    const uint32_t b_col =((lane>>3)&1)*16;
    const int NCH=H_DIM/32;  // 32
    for(int kt=0;kt<NCH;++kt){
        const int buf=kt&1;
        CP_WAIT0();
        __syncthreads();                 // single barrier per K-step
        if(kt+1<NCH) load_stage((kt+1)*32, buf^1);
#pragma unroll
        for(int ks=0;ks<2;++ks){
            uint32_t ah[2][4], al[2][4];
#pragma unroll
            for(int mt=0;mt<2;++mt){
                uint32_t ra=a_r+mt*16;
                ldsm4(ah[mt], sb + A1_OFF(buf,0) + ra*ROWB + ks*32 + a_c);
                ldsm4(al[mt], sb + A1_OFF(buf,1) + ra*ROWB + ks*32 + a_c);
            }
#pragma unroll
            for(int ntp=0;ntp<2;++ntp){
                uint32_t boff=(uint32_t)((wn*32+ntp*16+b_row8)*ROWB + ks*32 + b_col);
                uint32_t q1h[4],q1l[4],q3h[4],q3l[4];
                ldsm4(q1h, sb + B1_OFF(buf,0) + boff);
                ldsm4(q1l, sb + B1_OFF(buf,1) + boff);
                ldsm4(q3h, sb + B1_OFF(buf,2) + boff);
                ldsm4(q3l, sb + B1_OFF(buf,3) + boff);
#pragma unroll
                for(int mt=0;mt<2;++mt){
#pragma unroll
                    for(int half=0;half<2;++half){
                        int nt=ntp*2+half;
                        mma_bf16(acc1[mt][nt], ah[mt], q1h+half*2);
                        mma_bf16(acc1[mt][nt], ah[mt], q1l+half*2);
                        mma_bf16(acc1[mt][nt], al[mt], q1h+half*2);
                        mma_bf16(acc3[mt][nt], ah[mt], q3h+half*2);
                        mma_bf16(acc3[mt][nt], ah[mt], q3l+half*2);
                        mma_bf16(acc3[mt][nt], al[mt], q3h+half*2);
                    }
                }
            }
        }
    }

    const int eoff=g_off[e];
#pragma unroll
    for(int mt=0;mt<2;++mt)
#pragma unroll
    for(int nt=0;nt<4;++nt){
        int mbase=m0 + wm*32 + mt*16 + (lane>>2);
        int col  =n0 + wn*32 + nt*8 + (lane&3)*2;
#pragma unroll
        for(int h2=0;h2<2;++h2){
            int m=mbase+h2*8;
            if(m<cnt){
                float s0=acc1[mt][nt][h2*2], s1=acc1[mt][nt][h2*2+1];
                float v0=(s0/(1.f+expf(-s0)))*acc3[mt][nt][h2*2];
                float v1=(s1/(1.f+expf(-s1)))*acc3[mt][nt][h2*2+1];
                __nv_bfloat16 h0=__float2bfloat16_rn(v0), h1=__float2bfloat16_rn(v1);
                __nv_bfloat162 hv; hv.x=h0; hv.y=h1;
                __nv_bfloat162 lv;
                lv.x=__float2bfloat16_rn(v0-__bfloat162float(h0));
                lv.y=__float2bfloat16_rn(v1-__bfloat162float(h1));
                size_t o=((size_t)(eoff+m))*I_DIM+col;
                *(__nv_bfloat162*)(g_hhi+o)=hv;
                *(__nv_bfloat162*)(g_hlo+o)=lv;
            }
        }
    }
}

// ---------------- 5) GEMM2 (mma.sync): y[slot] = h @ w2 ----------------------
#define A2_OFF(st,t) (((st)*2+(t))*10240)
#define B2_OFF(st,t) (40960 + ((st)*2+(t))*10240)
#define G2_SMEM 81920

__global__ void __launch_bounds__(256,2) moe_gemm2_mma(){
    const int e=blockIdx.z, cnt=g_counts[e];
    const int m0=blockIdx.y*128; if(m0>=cnt) return;
    const int n0=blockIdx.x*128;
    const int tid=threadIdx.x, lane=tid&31, wid=tid>>5;
    const int wm=wid&3, wn=wid>>2;
    extern __shared__ char sm[];
    uint32_t sb=smem_u32(sm);

    const int slot0=g_off[e]+m0;
    const size_t ebase=(size_t)e*H_DIM*I_DIM;
    const int c8=(tid&3)*8, c16=(tid&3)*16, lrow=tid>>2;

    auto load_stage=[&](int k0,int st){
#pragma unroll
        for(int half=0; half<2; ++half){
            int row=lrow+half*64;
            size_t ao=(size_t)(slot0+row)*I_DIM + k0 + c8;
            cp16(sb + A2_OFF(st,0) + row*ROWB + c16, g_hhi+ao);
            cp16(sb + A2_OFF(st,1) + row*ROWB + c16, g_hlo+ao);
            size_t bo=ebase+(size_t)(n0+row)*I_DIM + k0 + c8;
            cp16(sb + B2_OFF(st,0) + row*ROWB + c16, g_w2hi+bo);
            cp16(sb + B2_OFF(st,1) + row*ROWB + c16, g_w2lo+bo);
        }
        CP_COMMIT();
    };

    float acc[2][8][4];
#pragma unroll
    for(int i=0;i<2;++i)
#pragma unroll
    for(int j=0;j<8;++j)
#pragma unroll
    for(int k=0;k<4;++k) acc[i][j][k]=0.f;

    load_stage(0,0);
    const uint32_t a_r=(uint32_t)(wm*32+(lane&15)), a_c=((lane>>4)&1)*16;
    const uint32_t b_row8=(uint32_t)((lane&7) + ((lane>>4)&1)*8);
    const uint32_t b_col =((lane>>3)&1)*16;
    const int NCH=I_DIM/32;  // 128
    for(int kt=0;kt<NCH;++kt){
        const int buf=kt&1;
        CP_WAIT0();
        __syncthreads();                 // single barrier per K-step
        if(kt+1<NCH) load_stage((kt+1)*32, buf^1);
#pragma unroll
        for(int ks=0;ks<2;++ks){
            uint32_t ah[2][4], al[2][4];
#pragma unroll
            for(int mt=0;mt<2;++mt){
                uint32_t ra=a_r+mt*16;
                ldsm4(ah[mt], sb + A2_OFF(buf,0) + ra*ROWB + ks*32 + a_c);
                ldsm4(al[mt], sb + A2_OFF(buf,1) + ra*ROWB + ks*32 + a_c);
            }
#pragma unroll
            for(int ntp=0;ntp<4;++ntp){
                uint32_t boff=(uint32_t)((wn*64+ntp*16+b_row8)*ROWB + ks*32 + b_col);
                uint32_t qh[4], ql[4];
                ldsm4(qh, sb + B2_OFF(buf,0) + boff);
                ldsm4(ql, sb + B2_OFF(buf,1) + boff);
#pragma unroll
                for(int mt=0;mt<2;++mt){
#pragma unroll
                    for(int half=0;half<2;++half){
                        int nt=ntp*2+half;
                        mma_bf16(acc[mt][nt], ah[mt], qh+half*2);
                        mma_bf16(acc[mt][nt], ah[mt], ql+half*2);
                        mma_bf16(acc[mt][nt], al[mt], qh+half*2);
                    }
                }
            }
        }
    }

    // plain float2 stores to per-slot buffer (no atomics)
#pragma unroll
    for(int mt=0;mt<2;++mt)
#pragma unroll
    for(int nt=0;nt<8;++nt){
        int lr0=wm*32+mt*16+(lane>>2);
        int col=n0 + wn*64 + nt*8 + (lane&3)*2;
#pragma unroll
        for(int h2=0;h2<2;++h2){
            int lr=lr0+h2*8;
            if(m0+lr<cnt){
                float2 v; v.x=acc[mt][nt][h2*2]; v.y=acc[mt][nt][h2*2+1];
                *(float2*)(g_y+(size_t)(slot0+lr)*H_DIM+col)=v;
            }
        }
    }
}

// ---------------- 6) combine: out[t] = w0*y[slot0] + w1*y[slot1] -------------
__global__ void combine_kernel(float* __restrict__ Out, int T){
    int idx=blockIdx.x*blockDim.x+threadIdx.x;
    int total=T*(H_DIM/4);
    if(idx>=total) return;
    int t=idx/(H_DIM/4), q=idx%(H_DIM/4);
    unsigned s0=g_slotinfo[2*t], s1=g_slotinfo[2*t+1];
    float w0=g_top_w[2*t], w1=g_top_w[2*t+1];
    int sl0=g_off[s0>>13]+(int)(s0&8191);
    int sl1=g_off[s1>>13]+(int)(s1&8191);
    float4 a=*(const float4*)(g_y+(size_t)sl0*H_DIM+q*4);
    float4 b=*(const float4*)(g_y+(size_t)sl1*H_DIM+q*4);
    float4 o;
    o.x=w0*a.x+w1*b.x; o.y=w0*a.y+w1*b.y;
    o.z=w0*a.z+w1*b.z; o.w=w0*a.w+w1*b.w;
    *(float4*)(Out+(size_t)t*H_DIM+q*4)=o;
}

// ---------------- launch ------------------------------------------------------
extern "C" void kernel_launch(void* const* d_in, const int* in_sizes, int n_in,
                              void* d_out, int out_size){
    const float* x =(const float*)d_in[0];
    const float* gw=(const float*)d_in[1];
    const float* w1=(const float*)d_in[2];
    const float* w3=(const float*)d_in[3];
    const float* w2=(const float*)d_in[4];
    float* out=(float*)d_out;
    const int T=in_sizes[0]/H_DIM;

    cudaFuncSetAttribute(moe_gemm1_mma, cudaFuncAttributeMaxDynamicSharedMemorySize, G1_SMEM);
    cudaFuncSetAttribute(moe_gemm2_mma, cudaFuncAttributeMaxDynamicSharedMemorySize, G2_SMEM);

    router_kernel<<<(T+7)/8,256>>>(x,gw,T);
    build_lists_kernel<<<E_NUM,256>>>(T);
    prep_kernel<<<49152,dim3(32,8)>>>(w1,w3,w2);
    const int mt=(T+127)/128;
    moe_gemm1_mma<<<dim3(I_DIM/64,  mt, E_NUM),256,G1_SMEM>>>();
    moe_gemm2_mma<<<dim3(H_DIM/128, mt, E_NUM),256,G2_SMEM>>>();
    combine_kernel<<<(T*(H_DIM/4)+255)/256,256>>>(out,T);
}

// round 16
// speedup vs baseline: 1.1121x; 1.1121x over previous
#include <cuda_runtime.h>
#include <cuda_bf16.h>
#include <cuda_fp16.h>
#include <math.h>
#include <stdint.h>

#define H_DIM 1024
#define E_NUM 8
#define I_DIM 4096
#define T_MAX 8192
#define SLOTS (2*T_MAX)

// ---------------- device scratch (no allocations allowed) -------------------
__device__ int      g_top_idx [T_MAX*2];
__device__ float    g_top_w   [T_MAX*2];
__device__ int      g_counts  [E_NUM];
__device__ int      g_off     [E_NUM];
__device__ int      g_tok     [E_NUM*T_MAX];
__device__ unsigned g_slotinfo[T_MAX*2];           // (e<<13)|pos per (token,k)
__device__ __nv_bfloat16 g_xhi [(size_t)T_MAX*H_DIM];
__device__ __nv_bfloat16 g_xlo [(size_t)T_MAX*H_DIM];
__device__ __nv_bfloat16 g_w1hi[(size_t)E_NUM*I_DIM*H_DIM]; // [E][I][H] K-major
__device__ __nv_bfloat16 g_w1lo[(size_t)E_NUM*I_DIM*H_DIM];
__device__ __nv_bfloat16 g_w3hi[(size_t)E_NUM*I_DIM*H_DIM];
__device__ __nv_bfloat16 g_w3lo[(size_t)E_NUM*I_DIM*H_DIM];
__device__ __half        g_w2hi[(size_t)E_NUM*H_DIM*I_DIM]; // [E][H][I] K-major fp16
__device__ __half        g_w2lo[(size_t)E_NUM*H_DIM*I_DIM];
__device__ __half        g_h16 [(size_t)(SLOTS+128)*I_DIM]; // SwiGLU out, fp16
__device__ float         g_y   [(size_t)(SLOTS+128)*H_DIM]; // expert outputs

// ---------------- PTX helpers (baseline sm_80 features only) -----------------
__device__ __forceinline__ uint32_t smem_u32(const void* p){
    uint32_t a; asm("{ .reg .u64 t; cvta.to.shared.u64 t, %1; cvt.u32.u64 %0, t; }":"=r"(a):"l"(p)); return a;
}
__device__ __forceinline__ void cp16(uint32_t s, const void* g){
    uint64_t ga; asm("cvta.to.global.u64 %0, %1;" : "=l"(ga) : "l"(g));
    asm volatile("cp.async.cg.shared.global [%0], [%1], 16;" :: "r"(s), "l"(ga) : "memory");
}
#define CP_COMMIT() asm volatile("cp.async.commit_group;":::"memory")
#define CP_WAIT0()  asm volatile("cp.async.wait_group 0;":::"memory")

__device__ __forceinline__ void ldsm4(uint32_t* r, uint32_t a){
    asm volatile("ldmatrix.sync.aligned.m8n8.x4.shared.b16 {%0,%1,%2,%3}, [%4];"
        : "=r"(r[0]),"=r"(r[1]),"=r"(r[2]),"=r"(r[3]) : "r"(a));
}
__device__ __forceinline__ void mma_bf16(float* c, const uint32_t* a, const uint32_t* b){
    asm volatile("mma.sync.aligned.m16n8k16.row.col.f32.bf16.bf16.f32 "
        "{%0,%1,%2,%3}, {%4,%5,%6,%7}, {%8,%9}, {%0,%1,%2,%3};"
        : "+f"(c[0]),"+f"(c[1]),"+f"(c[2]),"+f"(c[3])
        : "r"(a[0]),"r"(a[1]),"r"(a[2]),"r"(a[3]), "r"(b[0]),"r"(b[1]));
}
__device__ __forceinline__ void mma_f16(float* c, const uint32_t* a, const uint32_t* b){
    asm volatile("mma.sync.aligned.m16n8k16.row.col.f32.f16.f16.f32 "
        "{%0,%1,%2,%3}, {%4,%5,%6,%7}, {%8,%9}, {%0,%1,%2,%3};"
        : "+f"(c[0]),"+f"(c[1]),"+f"(c[2]),"+f"(c[3])
        : "r"(a[0]),"r"(a[1]),"r"(a[2]),"r"(a[3]), "r"(b[0]),"r"(b[1]));
}

// ---------------- 1) router + fused x hi/lo split -----------------------------
__global__ void router_kernel(const float* __restrict__ X, const float* __restrict__ GW, int T){
    int t=(blockIdx.x*blockDim.x+threadIdx.x)>>5, lane=threadIdx.x&31;
    if(t>=T) return;
    const float* xr=X+(size_t)t*H_DIM;
    float acc[E_NUM];
#pragma unroll
    for(int e=0;e<E_NUM;++e) acc[e]=0.f;
    for(int k=lane;k<H_DIM;k+=32){
        float xv=__ldg(xr+k);
        __nv_bfloat16 h=__float2bfloat16_rn(xv);
        g_xhi[(size_t)t*H_DIM+k]=h;
        g_xlo[(size_t)t*H_DIM+k]=__float2bfloat16_rn(xv-__bfloat162float(h));
        float4 g0=*(const float4*)(GW+(size_t)k*E_NUM), g1=*(const float4*)(GW+(size_t)k*E_NUM+4);
        acc[0]+=xv*g0.x; acc[1]+=xv*g0.y; acc[2]+=xv*g0.z; acc[3]+=xv*g0.w;
        acc[4]+=xv*g1.x; acc[5]+=xv*g1.y; acc[6]+=xv*g1.z; acc[7]+=xv*g1.w;
    }
#pragma unroll
    for(int o=16;o>0;o>>=1)
#pragma unroll
        for(int e=0;e<E_NUM;++e) acc[e]+=__shfl_xor_sync(0xffffffffu,acc[e],o);
    if(lane==0){
        int i1=0;
#pragma unroll
        for(int e=1;e<E_NUM;++e) if(acc[e]>acc[i1]) i1=e;
        int i2=(i1==0)?1:0;
#pragma unroll
        for(int e=0;e<E_NUM;++e) if(e!=i1&&acc[e]>acc[i2]) i2=e;
        float d=expf(acc[i2]-acc[i1]);
        g_top_idx[2*t]=i1;   g_top_w[2*t]=1.f/(1.f+d);
        g_top_idx[2*t+1]=i2; g_top_w[2*t+1]=d/(1.f+d);
    }
}

// ---------------- 2) deterministic per-expert compaction ---------------------
__global__ void build_lists_kernel(int T){
    const int e=blockIdx.x, tid=threadIdx.x, lane=tid&31, wid=tid>>5;
    __shared__ int s_wsum[8]; __shared__ int s_base;
    if(tid==0) s_base=0;
    __syncthreads();
    for(int st=0;st<T;st+=256){
        int t=st+tid, flag=0, kidx=0;
        if(t<T){
            if(g_top_idx[2*t]==e){flag=1;kidx=0;}
            else if(g_top_idx[2*t+1]==e){flag=1;kidx=1;}
        }
        unsigned m=__ballot_sync(0xffffffffu,flag);
        if(lane==0) s_wsum[wid]=__popc(m);
        __syncthreads();
        int off=s_base;
        for(int i=0;i<wid;++i) off+=s_wsum[i];
        int pos=off+__popc(m&((1u<<lane)-1u));
        if(flag){
            g_tok[e*T_MAX+pos]=t;
            g_slotinfo[2*t+kidx]=((unsigned)e<<13)|(unsigned)pos;
        }
        __syncthreads();
        if(tid==0){ int tt=0;
#pragma unroll
            for(int i=0;i<8;++i) tt+=s_wsum[i];
            s_base+=tt; }
        __syncthreads();
    }
    if(tid==0) g_counts[e]=s_base;
}

// ---------------- 3) weight transposes+splits (one kernel) -------------------
// [0,16384) w1 -> bf16, [16384,32768) w3 -> bf16, [32768,49152) w2 -> fp16.
__global__ void prep_kernel(const float* __restrict__ w1, const float* __restrict__ w3,
                            const float* __restrict__ w2){
    if(blockIdx.x==0 && threadIdx.x==0 && threadIdx.y==0){
        int s=0;
#pragma unroll
        for(int e=0;e<E_NUM;++e){ g_off[e]=s; s+=g_counts[e]; }
    }
    int bid=blockIdx.x;
    __shared__ float s[64][33];
    int tx=threadIdx.x, ty=threadIdx.y;  // 32x8
    if(bid<32768){
        bool is1=bid<16384; int b=is1?bid:bid-16384;
        int e=b>>11; b&=2047; int bx=b&127, by=b>>7;       // C=I:128x, R=H:16y
        const int R=H_DIM, C=I_DIM;
        const float* src=(is1?w1:w3)+(size_t)e*R*C;
        __nv_bfloat16* dhi=(is1?g_w1hi:g_w3hi)+(size_t)e*R*C;
        __nv_bfloat16* dlo=(is1?g_w1lo:g_w3lo)+(size_t)e*R*C;
        int r0=by*64, c0=bx*32;
#pragma unroll
        for(int i=ty;i<64;i+=8) s[i][tx]=src[(size_t)(r0+i)*C+c0+tx];
        __syncthreads();
#pragma unroll
        for(int i=ty;i<32;i+=8){
            float v0=s[2*tx][i], v1=s[2*tx+1][i];
            __nv_bfloat16 h0=__float2bfloat16_rn(v0), h1=__float2bfloat16_rn(v1);
            __nv_bfloat162 hv; hv.x=h0; hv.y=h1;
            __nv_bfloat162 lv;
            lv.x=__float2bfloat16_rn(v0-__bfloat162float(h0));
            lv.y=__float2bfloat16_rn(v1-__bfloat162float(h1));
            size_t o=(size_t)(c0+i)*R+r0+2*tx;
            *(__nv_bfloat162*)(dhi+o)=hv;
            *(__nv_bfloat162*)(dlo+o)=lv;
        }
    } else {
        int b=bid-32768; int e=b>>11; b&=2047; int bx=b&31, by=b>>5; // C=H:32x, R=I:64y
        const int R=I_DIM, C=H_DIM;
        const float* src=w2+(size_t)e*R*C;
        __half* dhi=g_w2hi+(size_t)e*R*C;
        __half* dlo=g_w2lo+(size_t)e*R*C;
        int r0=by*64, c0=bx*32;
#pragma unroll
        for(int i=ty;i<64;i+=8) s[i][tx]=src[(size_t)(r0+i)*C+c0+tx];
        __syncthreads();
#pragma unroll
        for(int i=ty;i<32;i+=8){
            float v0=s[2*tx][i], v1=s[2*tx+1][i];
            __half h0=__float2half_rn(v0), h1=__float2half_rn(v1);
            __half2 hv; hv.x=h0; hv.y=h1;
            __half2 lv;
            lv.x=__float2half_rn(v0-__half2float(h0));
            lv.y=__float2half_rn(v1-__half2float(h1));
            size_t o=(size_t)(c0+i)*R+r0+2*tx;
            *(__half2*)(dhi+o)=hv;
            *(__half2*)(dlo+o)=lv;
        }
    }
}

// ---------------- 4) GEMM1 (mma.sync bf16x3): h = silu(x@w1)*(x@w3) ----------
// Term-major MMA ordering: same-acc MMAs are >=8 apart (hides MMA latency).
#define ROWB 80
#define A1_OFF(st,t) (512   + ((st)*2+(t))*10240)
#define B1_OFF(st,t) (41472 + ((st)*4+(t))*5120)
#define G1_SMEM 82432

__global__ void __launch_bounds__(256,2) moe_gemm1_mma(){
    const int e=blockIdx.z, cnt=g_counts[e];
    const int m0=blockIdx.y*128; if(m0>=cnt) return;
    const int n0=blockIdx.x*64;
    const int tid=threadIdx.x, lane=tid&31, wid=tid>>5;
    const int wm=wid&3, wn=wid>>2;
    extern __shared__ char sm[];
    uint32_t sb=smem_u32(sm);
    int* s_tok=(int*)sm;
    if(tid<128){ int r=m0+tid; s_tok[tid]=g_tok[e*T_MAX+(r<cnt?r:cnt-1)]; }
    __syncthreads();

    const size_t ebase=(size_t)e*I_DIM*H_DIM;
    const __nv_bfloat16* bsrc[4]={ g_w1hi+ebase+(size_t)n0*H_DIM, g_w1lo+ebase+(size_t)n0*H_DIM,
                                   g_w3hi+ebase+(size_t)n0*H_DIM, g_w3lo+ebase+(size_t)n0*H_DIM };
    const int c8=(tid&3)*8, c16=(tid&3)*16, lrow=tid>>2;

    auto load_stage=[&](int k0,int st){
#pragma unroll
        for(int half=0; half<2; ++half){
            int row=lrow+half*64;
            size_t so=(size_t)s_tok[row]*H_DIM + k0 + c8;
            cp16(sb + A1_OFF(st,0) + row*ROWB + c16, g_xhi+so);
            cp16(sb + A1_OFF(st,1) + row*ROWB + c16, g_xlo+so);
        }
#pragma unroll
        for(int t=0;t<4;++t)
            cp16(sb + B1_OFF(st,t) + lrow*ROWB + c16, bsrc[t]+(size_t)lrow*H_DIM + k0 + c8);
        CP_COMMIT();
    };

    float acc1[2][4][4], acc3[2][4][4];
#pragma unroll
    for(int i=0;i<2;++i)
#pragma unroll
    for(int j=0;j<4;++j)
#pragma unroll
    for(int k=0;k<4;++k){ acc1[i][j][k]=0.f; acc3[i][j][k]=0.f; }

    load_stage(0,0);
    const uint32_t a_r=(uint32_t)(wm*32+(lane&15)), a_c=((lane>>4)&1)*16;
    const uint32_t b_row8=(uint32_t)((lane&7) + ((lane>>4)&1)*8);
    const uint32_t b_col =((lane>>3)&1)*16;
    const int NCH=H_DIM/32;  // 32
    for(int kt=0;kt<NCH;++kt){
        const int buf=kt&1;
        CP_WAIT0();
        __syncthreads();
        if(kt+1<NCH) load_stage((kt+1)*32, buf^1);
#pragma unroll
        for(int ks=0;ks<2;++ks){
            uint32_t ah[2][4], al[2][4];
#pragma unroll
            for(int mt=0;mt<2;++mt){
                uint32_t ra=a_r+mt*16;
                ldsm4(ah[mt], sb + A1_OFF(buf,0) + ra*ROWB + ks*32 + a_c);
                ldsm4(al[mt], sb + A1_OFF(buf,1) + ra*ROWB + ks*32 + a_c);
            }
#pragma unroll
            for(int ntp=0;ntp<2;++ntp){
                uint32_t boff=(uint32_t)((wn*32+ntp*16+b_row8)*ROWB + ks*32 + b_col);
                uint32_t q1h[4],q1l[4],q3h[4],q3l[4];
                ldsm4(q1h, sb + B1_OFF(buf,0) + boff);
                ldsm4(q1l, sb + B1_OFF(buf,1) + boff);
                ldsm4(q3h, sb + B1_OFF(buf,2) + boff);
                ldsm4(q3l, sb + B1_OFF(buf,3) + boff);
                // term hh (8 independent MMAs)
#pragma unroll
                for(int mt=0;mt<2;++mt)
#pragma unroll
                for(int half=0;half<2;++half){
                    int nt=ntp*2+half;
                    mma_bf16(acc1[mt][nt], ah[mt], q1h+half*2);
                    mma_bf16(acc3[mt][nt], ah[mt], q3h+half*2);
                }
                // term hl
#pragma unroll
                for(int mt=0;mt<2;++mt)
#pragma unroll
                for(int half=0;half<2;++half){
                    int nt=ntp*2+half;
                    mma_bf16(acc1[mt][nt], ah[mt], q1l+half*2);
                    mma_bf16(acc3[mt][nt], ah[mt], q3l+half*2);
                }
                // term lh
#pragma unroll
                for(int mt=0;mt<2;++mt)
#pragma unroll
                for(int half=0;half<2;++half){
                    int nt=ntp*2+half;
                    mma_bf16(acc1[mt][nt], al[mt], q1h+half*2);
                    mma_bf16(acc3[mt][nt], al[mt], q3h+half*2);
                }
            }
        }
    }

    // SwiGLU epilogue -> fp16 h
    const int eoff=g_off[e];
#pragma unroll
    for(int mt=0;mt<2;++mt)
#pragma unroll
    for(int nt=0;nt<4;++nt){
        int mbase=m0 + wm*32 + mt*16 + (lane>>2);
        int col  =n0 + wn*32 + nt*8 + (lane&3)*2;
#pragma unroll
        for(int h2=0;h2<2;++h2){
            int m=mbase+h2*8;
            if(m<cnt){
                float s0=acc1[mt][nt][h2*2], s1=acc1[mt][nt][h2*2+1];
                float v0=(s0/(1.f+expf(-s0)))*acc3[mt][nt][h2*2];
                float v1=(s1/(1.f+expf(-s1)))*acc3[mt][nt][h2*2+1];
                __half2 hv; hv.x=__float2half_rn(v0); hv.y=__float2half_rn(v1);
                *(__half2*)(g_h16+((size_t)(eoff+m))*I_DIM+col)=hv;
            }
        }
    }
}

// ---------------- 5) GEMM2 (mma.sync fp16x2): y[slot] = h @ w2 ---------------
#define A2_OFF(st)   ((st)*10240)
#define B2_OFF(st,t) (20480 + ((st)*2+(t))*10240)
#define G2_SMEM 61440

__global__ void __launch_bounds__(256,2) moe_gemm2_mma(){
    const int e=blockIdx.z, cnt=g_counts[e];
    const int m0=blockIdx.y*128; if(m0>=cnt) return;
    const int n0=blockIdx.x*128;
    const int tid=threadIdx.x, lane=tid&31, wid=tid>>5;
    const int wm=wid&3, wn=wid>>2;
    extern __shared__ char sm[];
    uint32_t sb=smem_u32(sm);

    const int slot0=g_off[e]+m0;
    const size_t ebase=(size_t)e*H_DIM*I_DIM;
    const int c8=(tid&3)*8, c16=(tid&3)*16, lrow=tid>>2;

    auto load_stage=[&](int k0,int st){
#pragma unroll
        for(int half=0; half<2; ++half){
            int row=lrow+half*64;
            cp16(sb + A2_OFF(st) + row*ROWB + c16,
                 g_h16+(size_t)(slot0+row)*I_DIM + k0 + c8);
            size_t bo=ebase+(size_t)(n0+row)*I_DIM + k0 + c8;
            cp16(sb + B2_OFF(st,0) + row*ROWB + c16, g_w2hi+bo);
            cp16(sb + B2_OFF(st,1) + row*ROWB + c16, g_w2lo+bo);
        }
        CP_COMMIT();
    };

    float acc[2][8][4];
#pragma unroll
    for(int i=0;i<2;++i)
#pragma unroll
    for(int j=0;j<8;++j)
#pragma unroll
    for(int k=0;k<4;++k) acc[i][j][k]=0.f;

    load_stage(0,0);
    const uint32_t a_r=(uint32_t)(wm*32+(lane&15)), a_c=((lane>>4)&1)*16;
    const uint32_t b_row8=(uint32_t)((lane&7) + ((lane>>4)&1)*8);
    const uint32_t b_col =((lane>>3)&1)*16;
    const int NCH=I_DIM/32;  // 128
    for(int kt=0;kt<NCH;++kt){
        const int buf=kt&1;
        CP_WAIT0();
        __syncthreads();
        if(kt+1<NCH) load_stage((kt+1)*32, buf^1);
#pragma unroll
        for(int ks=0;ks<2;++ks){
            uint32_t ah[2][4];
#pragma unroll
            for(int mt=0;mt<2;++mt)
                ldsm4(ah[mt], sb + A2_OFF(buf) + (a_r+mt*16)*ROWB + ks*32 + a_c);
#pragma unroll
            for(int ntp=0;ntp<4;++ntp){
                uint32_t boff=(uint32_t)((wn*64+ntp*16+b_row8)*ROWB + ks*32 + b_col);
                uint32_t qh[4], ql[4];
                ldsm4(qh, sb + B2_OFF(buf,0) + boff);
                ldsm4(ql, sb + B2_OFF(buf,1) + boff);
                // term h (4 independent MMAs)
#pragma unroll
                for(int mt=0;mt<2;++mt)
#pragma unroll
                for(int half=0;half<2;++half)
                    mma_f16(acc[mt][ntp*2+half], ah[mt], qh+half*2);
                // term l
#pragma unroll
                for(int mt=0;mt<2;++mt)
#pragma unroll
                for(int half=0;half<2;++half)
                    mma_f16(acc[mt][ntp*2+half], ah[mt], ql+half*2);
            }
        }
    }

#pragma unroll
    for(int mt=0;mt<2;++mt)
#pragma unroll
    for(int nt=0;nt<8;++nt){
        int lr0=wm*32+mt*16+(lane>>2);
        int col=n0 + wn*64 + nt*8 + (lane&3)*2;
#pragma unroll
        for(int h2=0;h2<2;++h2){
            int lr=lr0+h2*8;
            if(m0+lr<cnt){
                float2 v; v.x=acc[mt][nt][h2*2]; v.y=acc[mt][nt][h2*2+1];
                *(float2*)(g_y+(size_t)(slot0+lr)*H_DIM+col)=v;
            }
        }
    }
}

// ---------------- 6) combine: out[t] = w0*y[slot0] + w1*y[slot1] -------------
__global__ void combine_kernel(float* __restrict__ Out, int T){
    int idx=blockIdx.x*blockDim.x+threadIdx.x;
    int total=T*(H_DIM/4);
    if(idx>=total) return;
    int t=idx/(H_DIM/4), q=idx%(H_DIM/4);
    unsigned s0=g_slotinfo[2*t], s1=g_slotinfo[2*t+1];
    float w0=g_top_w[2*t], w1=g_top_w[2*t+1];
    int sl0=g_off[s0>>13]+(int)(s0&8191);
    int sl1=g_off[s1>>13]+(int)(s1&8191);
    float4 a=*(const float4*)(g_y+(size_t)sl0*H_DIM+q*4);
    float4 b=*(const float4*)(g_y+(size_t)sl1*H_DIM+q*4);
    float4 o;
    o.x=w0*a.x+w1*b.x; o.y=w0*a.y+w1*b.y;
    o.z=w0*a.z+w1*b.z; o.w=w0*a.w+w1*b.w;
    *(float4*)(Out+(size_t)t*H_DIM+q*4)=o;
}

// ---------------- launch ------------------------------------------------------
extern "C" void kernel_launch(void* const* d_in, const int* in_sizes, int n_in,
                              void* d_out, int out_size){
    const float* x =(const float*)d_in[0];
    const float* gw=(const float*)d_in[1];
    const float* w1=(const float*)d_in[2];
    const float* w3=(const float*)d_in[3];
    const float* w2=(const float*)d_in[4];
    float* out=(float*)d_out;
    const int T=in_sizes[0]/H_DIM;

    cudaFuncSetAttribute(moe_gemm1_mma, cudaFuncAttributeMaxDynamicSharedMemorySize, G1_SMEM);
    cudaFuncSetAttribute(moe_gemm2_mma, cudaFuncAttributeMaxDynamicSharedMemorySize, G2_SMEM);

    router_kernel<<<(T+7)/8,256>>>(x,gw,T);
    build_lists_kernel<<<E_NUM,256>>>(T);
    prep_kernel<<<49152,dim3(32,8)>>>(w1,w3,w2);
    const int mt=(T+127)/128;
    moe_gemm1_mma<<<dim3(I_DIM/64,  mt, E_NUM),256,G1_SMEM>>>();
    moe_gemm2_mma<<<dim3(H_DIM/128, mt, E_NUM),256,G2_SMEM>>>();
    combine_kernel<<<(T*(H_DIM/4)+255)/256,256>>>(out,T);
}

// round 17
// speedup vs baseline: 1.3514x; 1.2152x over previous
#include <cuda_runtime.h>
#include <cuda_bf16.h>
#include <cuda_fp16.h>
#include <math.h>
#include <stdint.h>

#define H_DIM 1024
#define E_NUM 8
#define I_DIM 4096
#define T_MAX 8192
#define SLOTS (2*T_MAX)

// ---------------- device scratch (no allocations allowed) -------------------
__device__ int      g_top_idx [T_MAX*2];
__device__ float    g_top_w   [T_MAX*2];
__device__ int      g_counts  [E_NUM];
__device__ int      g_off     [E_NUM];
__device__ int      g_tok     [E_NUM*T_MAX];
__device__ unsigned g_slotinfo[T_MAX*2];           // (e<<13)|pos per (token,k)
__device__ __half   g_x16 [(size_t)T_MAX*H_DIM];   // x, fp16
__device__ __half   g_w1hi[(size_t)E_NUM*I_DIM*H_DIM]; // [E][I][H] K-major fp16
__device__ __half   g_w1lo[(size_t)E_NUM*I_DIM*H_DIM];
__device__ __half   g_w3hi[(size_t)E_NUM*I_DIM*H_DIM];
__device__ __half   g_w3lo[(size_t)E_NUM*I_DIM*H_DIM];
__device__ __half   g_w2hi[(size_t)E_NUM*H_DIM*I_DIM]; // [E][H][I] K-major fp16
__device__ __half   g_w2lo[(size_t)E_NUM*H_DIM*I_DIM];
__device__ __half   g_h16 [(size_t)(SLOTS+128)*I_DIM]; // SwiGLU out, fp16
__device__ float    g_y   [(size_t)(SLOTS+128)*H_DIM]; // expert outputs

// ---------------- PTX helpers (baseline sm_80 features only) -----------------
__device__ __forceinline__ uint32_t smem_u32(const void* p){
    uint32_t a; asm("{ .reg .u64 t; cvta.to.shared.u64 t, %1; cvt.u32.u64 %0, t; }":"=r"(a):"l"(p)); return a;
}
__device__ __forceinline__ void cp16(uint32_t s, const void* g){
    uint64_t ga; asm("cvta.to.global.u64 %0, %1;" : "=l"(ga) : "l"(g));
    asm volatile("cp.async.cg.shared.global [%0], [%1], 16;" :: "r"(s), "l"(ga) : "memory");
}
#define CP_COMMIT() asm volatile("cp.async.commit_group;":::"memory")
#define CP_WAIT0()  asm volatile("cp.async.wait_group 0;":::"memory")

__device__ __forceinline__ void ldsm4(uint32_t* r, uint32_t a){
    asm volatile("ldmatrix.sync.aligned.m8n8.x4.shared.b16 {%0,%1,%2,%3}, [%4];"
        : "=r"(r[0]),"=r"(r[1]),"=r"(r[2]),"=r"(r[3]) : "r"(a));
}
__device__ __forceinline__ void mma_f16(float* c, const uint32_t* a, const uint32_t* b){
    asm volatile("mma.sync.aligned.m16n8k16.row.col.f32.f16.f16.f32 "
        "{%0,%1,%2,%3}, {%4,%5,%6,%7}, {%8,%9}, {%0,%1,%2,%3};"
        : "+f"(c[0]),"+f"(c[1]),"+f"(c[2]),"+f"(c[3])
        : "r"(a[0]),"r"(a[1]),"r"(a[2]),"r"(a[3]), "r"(b[0]),"r"(b[1]));
}

// ---------------- 1) router + fused x fp16 convert ----------------------------
__global__ void router_kernel(const float* __restrict__ X, const float* __restrict__ GW, int T){
    int t=(blockIdx.x*blockDim.x+threadIdx.x)>>5, lane=threadIdx.x&31;
    if(t>=T) return;
    const float* xr=X+(size_t)t*H_DIM;
    float acc[E_NUM];
#pragma unroll
    for(int e=0;e<E_NUM;++e) acc[e]=0.f;
    for(int k=lane;k<H_DIM;k+=32){
        float xv=__ldg(xr+k);
        g_x16[(size_t)t*H_DIM+k]=__float2half_rn(xv);
        float4 g0=*(const float4*)(GW+(size_t)k*E_NUM), g1=*(const float4*)(GW+(size_t)k*E_NUM+4);
        acc[0]+=xv*g0.x; acc[1]+=xv*g0.y; acc[2]+=xv*g0.z; acc[3]+=xv*g0.w;
        acc[4]+=xv*g1.x; acc[5]+=xv*g1.y; acc[6]+=xv*g1.z; acc[7]+=xv*g1.w;
    }
#pragma unroll
    for(int o=16;o>0;o>>=1)
#pragma unroll
        for(int e=0;e<E_NUM;++e) acc[e]+=__shfl_xor_sync(0xffffffffu,acc[e],o);
    if(lane==0){
        int i1=0;
#pragma unroll
        for(int e=1;e<E_NUM;++e) if(acc[e]>acc[i1]) i1=e;
        int i2=(i1==0)?1:0;
#pragma unroll
        for(int e=0;e<E_NUM;++e) if(e!=i1&&acc[e]>acc[i2]) i2=e;
        float d=expf(acc[i2]-acc[i1]);
        g_top_idx[2*t]=i1;   g_top_w[2*t]=1.f/(1.f+d);
        g_top_idx[2*t+1]=i2; g_top_w[2*t+1]=d/(1.f+d);
    }
}

// ---------------- 2) deterministic per-expert compaction ---------------------
__global__ void build_lists_kernel(int T){
    const int e=blockIdx.x, tid=threadIdx.x, lane=tid&31, wid=tid>>5;
    __shared__ int s_wsum[8]; __shared__ int s_base;
    if(tid==0) s_base=0;
    __syncthreads();
    for(int st=0;st<T;st+=256){
        int t=st+tid, flag=0, kidx=0;
        if(t<T){
            if(g_top_idx[2*t]==e){flag=1;kidx=0;}
            else if(g_top_idx[2*t+1]==e){flag=1;kidx=1;}
        }
        unsigned m=__ballot_sync(0xffffffffu,flag);
        if(lane==0) s_wsum[wid]=__popc(m);
        __syncthreads();
        int off=s_base;
        for(int i=0;i<wid;++i) off+=s_wsum[i];
        int pos=off+__popc(m&((1u<<lane)-1u));
        if(flag){
            g_tok[e*T_MAX+pos]=t;
            g_slotinfo[2*t+kidx]=((unsigned)e<<13)|(unsigned)pos;
        }
        __syncthreads();
        if(tid==0){ int tt=0;
#pragma unroll
            for(int i=0;i<8;++i) tt+=s_wsum[i];
            s_base+=tt; }
        __syncthreads();
    }
    if(tid==0) g_counts[e]=s_base;
}

// ---------------- 3) weight transposes+splits to fp16 hi/lo ------------------
// [0,16384) w1, [16384,32768) w3, [32768,49152) w2.
__global__ void prep_kernel(const float* __restrict__ w1, const float* __restrict__ w3,
                            const float* __restrict__ w2){
    if(blockIdx.x==0 && threadIdx.x==0 && threadIdx.y==0){
        int s=0;
#pragma unroll
        for(int e=0;e<E_NUM;++e){ g_off[e]=s; s+=g_counts[e]; }
    }
    int bid=blockIdx.x;
    const float* src; __half *dhi,*dlo; int R,C,bx,by,e;
    if(bid<32768){
        bool is1=bid<16384; int b=is1?bid:bid-16384;
        e=b>>11; b&=2047; bx=b&127; by=b>>7;          // C=I:128x, R=H:16y(64-row tiles)
        R=H_DIM; C=I_DIM;
        src=(is1?w1:w3)+(size_t)e*R*C;
        dhi=(is1?g_w1hi:g_w3hi)+(size_t)e*R*C; dlo=(is1?g_w1lo:g_w3lo)+(size_t)e*R*C;
    } else {
        int b=bid-32768; e=b>>11; b&=2047; bx=b&31; by=b>>5;  // C=H:32x, R=I:64y
        R=I_DIM; C=H_DIM;
        src=w2+(size_t)e*R*C;
        dhi=g_w2hi+(size_t)e*R*C; dlo=g_w2lo+(size_t)e*R*C;
    }
    __shared__ float s[64][33];
    int r0=by*64, c0=bx*32, tx=threadIdx.x, ty=threadIdx.y;  // 32x8
#pragma unroll
    for(int i=ty;i<64;i+=8)
        s[i][tx]=src[(size_t)(r0+i)*C+c0+tx];
    __syncthreads();
#pragma unroll
    for(int i=ty;i<32;i+=8){
        float v0=s[2*tx][i], v1=s[2*tx+1][i];
        __half h0=__float2half_rn(v0), h1=__float2half_rn(v1);
        __half2 hv; hv.x=h0; hv.y=h1;
        __half2 lv;
        lv.x=__float2half_rn(v0-__half2float(h0));
        lv.y=__float2half_rn(v1-__half2float(h1));
        size_t o=(size_t)(c0+i)*R+r0+2*tx;
        *(__half2*)(dhi+o)=hv;
        *(__half2*)(dlo+o)=lv;
    }
}

// ---------------- 4) GEMM1 (fp16x2): h = silu(x@w1)*(x@w3) -------------------
// x single fp16 (A), w1/w3 fp16 hi+lo (B): 2 MMA terms per tile (was 3).
#define ROWB 80
#define A1_OFF(st)   (512 + (st)*10240)                 // 128 rows * 80B
#define B1_OFF(st,t) (20992 + ((st)*4+(t))*5120)        // 64 rows * 80B
#define G1_SMEM 61952

__global__ void __launch_bounds__(256,2) moe_gemm1_mma(){
    const int e=blockIdx.z, cnt=g_counts[e];
    const int m0=blockIdx.y*128; if(m0>=cnt) return;
    const int n0=blockIdx.x*64;
    const int tid=threadIdx.x, lane=tid&31, wid=tid>>5;
    const int wm=wid&3, wn=wid>>2;
    extern __shared__ char sm[];
    uint32_t sb=smem_u32(sm);
    int* s_tok=(int*)sm;
    if(tid<128){ int r=m0+tid; s_tok[tid]=g_tok[e*T_MAX+(r<cnt?r:cnt-1)]; }
    __syncthreads();

    const size_t ebase=(size_t)e*I_DIM*H_DIM;
    const __half* bsrc[4]={ g_w1hi+ebase+(size_t)n0*H_DIM, g_w1lo+ebase+(size_t)n0*H_DIM,
                            g_w3hi+ebase+(size_t)n0*H_DIM, g_w3lo+ebase+(size_t)n0*H_DIM };
    const int c8=(tid&3)*8, c16=(tid&3)*16, lrow=tid>>2;

    auto load_stage=[&](int k0,int st){
#pragma unroll
        for(int half=0; half<2; ++half){
            int row=lrow+half*64;
            cp16(sb + A1_OFF(st) + row*ROWB + c16,
                 g_x16+(size_t)s_tok[row]*H_DIM + k0 + c8);
        }
#pragma unroll
        for(int t=0;t<4;++t)
            cp16(sb + B1_OFF(st,t) + lrow*ROWB + c16, bsrc[t]+(size_t)lrow*H_DIM + k0 + c8);
        CP_COMMIT();
    };

    float acc1[2][4][4], acc3[2][4][4];
#pragma unroll
    for(int i=0;i<2;++i)
#pragma unroll
    for(int j=0;j<4;++j)
#pragma unroll
    for(int k=0;k<4;++k){ acc1[i][j][k]=0.f; acc3[i][j][k]=0.f; }

    load_stage(0,0);
    const uint32_t a_r=(uint32_t)(wm*32+(lane&15)), a_c=((lane>>4)&1)*16;
    const uint32_t b_row8=(uint32_t)((lane&7) + ((lane>>4)&1)*8);
    const uint32_t b_col =((lane>>3)&1)*16;
    const int NCH=H_DIM/32;  // 32
    for(int kt=0;kt<NCH;++kt){
        const int buf=kt&1;
        CP_WAIT0();
        __syncthreads();
        if(kt+1<NCH) load_stage((kt+1)*32, buf^1);
#pragma unroll
        for(int ks=0;ks<2;++ks){
            uint32_t ah[2][4];
#pragma unroll
            for(int mt=0;mt<2;++mt)
                ldsm4(ah[mt], sb + A1_OFF(buf) + (a_r+mt*16)*ROWB + ks*32 + a_c);
#pragma unroll
            for(int ntp=0;ntp<2;++ntp){
                uint32_t boff=(uint32_t)((wn*32+ntp*16+b_row8)*ROWB + ks*32 + b_col);
                uint32_t q1h[4],q1l[4],q3h[4],q3l[4];
                ldsm4(q1h, sb + B1_OFF(buf,0) + boff);
                ldsm4(q1l, sb + B1_OFF(buf,1) + boff);
                ldsm4(q3h, sb + B1_OFF(buf,2) + boff);
                ldsm4(q3l, sb + B1_OFF(buf,3) + boff);
                // term hi (8 independent MMAs)
#pragma unroll
                for(int mt=0;mt<2;++mt)
#pragma unroll
                for(int half=0;half<2;++half){
                    int nt=ntp*2+half;
                    mma_f16(acc1[mt][nt], ah[mt], q1h+half*2);
                    mma_f16(acc3[mt][nt], ah[mt], q3h+half*2);
                }
                // term lo
#pragma unroll
                for(int mt=0;mt<2;++mt)
#pragma unroll
                for(int half=0;half<2;++half){
                    int nt=ntp*2+half;
                    mma_f16(acc1[mt][nt], ah[mt], q1l+half*2);
                    mma_f16(acc3[mt][nt], ah[mt], q3l+half*2);
                }
            }
        }
    }

    // SwiGLU epilogue -> fp16 h
    const int eoff=g_off[e];
#pragma unroll
    for(int mt=0;mt<2;++mt)
#pragma unroll
    for(int nt=0;nt<4;++nt){
        int mbase=m0 + wm*32 + mt*16 + (lane>>2);
        int col  =n0 + wn*32 + nt*8 + (lane&3)*2;
#pragma unroll
        for(int h2=0;h2<2;++h2){
            int m=mbase+h2*8;
            if(m<cnt){
                float s0=acc1[mt][nt][h2*2], s1=acc1[mt][nt][h2*2+1];
                float v0=(s0/(1.f+expf(-s0)))*acc3[mt][nt][h2*2];
                float v1=(s1/(1.f+expf(-s1)))*acc3[mt][nt][h2*2+1];
                __half2 hv; hv.x=__float2half_rn(v0); hv.y=__float2half_rn(v1);
                *(__half2*)(g_h16+((size_t)(eoff+m))*I_DIM+col)=hv;
            }
        }
    }
}

// ---------------- 5) GEMM2 (fp16x2): y[slot] = h @ w2 ------------------------
#define A2_OFF(st)   ((st)*10240)
#define B2_OFF(st,t) (20480 + ((st)*2+(t))*10240)
#define G2_SMEM 61440

__global__ void __launch_bounds__(256,2) moe_gemm2_mma(){
    const int e=blockIdx.z, cnt=g_counts[e];
    const int m0=blockIdx.y*128; if(m0>=cnt) return;
    const int n0=blockIdx.x*128;
    const int tid=threadIdx.x, lane=tid&31, wid=tid>>5;
    const int wm=wid&3, wn=wid>>2;
    extern __shared__ char sm[];
    uint32_t sb=smem_u32(sm);

    const int slot0=g_off[e]+m0;
    const size_t ebase=(size_t)e*H_DIM*I_DIM;
    const int c8=(tid&3)*8, c16=(tid&3)*16, lrow=tid>>2;

    auto load_stage=[&](int k0,int st){
#pragma unroll
        for(int half=0; half<2; ++half){
            int row=lrow+half*64;
            cp16(sb + A2_OFF(st) + row*ROWB + c16,
                 g_h16+(size_t)(slot0+row)*I_DIM + k0 + c8);
            size_t bo=ebase+(size_t)(n0+row)*I_DIM + k0 + c8;
            cp16(sb + B2_OFF(st,0) + row*ROWB + c16, g_w2hi+bo);
            cp16(sb + B2_OFF(st,1) + row*ROWB + c16, g_w2lo+bo);
        }
        CP_COMMIT();
    };

    float acc[2][8][4];
#pragma unroll
    for(int i=0;i<2;++i)
#pragma unroll
    for(int j=0;j<8;++j)
#pragma unroll
    for(int k=0;k<4;++k) acc[i][j][k]=0.f;

    load_stage(0,0);
    const uint32_t a_r=(uint32_t)(wm*32+(lane&15)), a_c=((lane>>4)&1)*16;
    const uint32_t b_row8=(uint32_t)((lane&7) + ((lane>>4)&1)*8);
    const uint32_t b_col =((lane>>3)&1)*16;
    const int NCH=I_DIM/32;  // 128
    for(int kt=0;kt<NCH;++kt){
        const int buf=kt&1;
        CP_WAIT0();
        __syncthreads();
        if(kt+1<NCH) load_stage((kt+1)*32, buf^1);
#pragma unroll
        for(int ks=0;ks<2;++ks){
            uint32_t ah[2][4];
#pragma unroll
            for(int mt=0;mt<2;++mt)
                ldsm4(ah[mt], sb + A2_OFF(buf) + (a_r+mt*16)*ROWB + ks*32 + a_c);
#pragma unroll
            for(int ntp=0;ntp<4;++ntp){
                uint32_t boff=(uint32_t)((wn*64+ntp*16+b_row8)*ROWB + ks*32 + b_col);
                uint32_t qh[4], ql[4];
                ldsm4(qh, sb + B2_OFF(buf,0) + boff);
                ldsm4(ql, sb + B2_OFF(buf,1) + boff);
#pragma unroll
                for(int mt=0;mt<2;++mt)
#pragma unroll
                for(int half=0;half<2;++half)
                    mma_f16(acc[mt][ntp*2+half], ah[mt], qh+half*2);
#pragma unroll
                for(int mt=0;mt<2;++mt)
#pragma unroll
                for(int half=0;half<2;++half)
                    mma_f16(acc[mt][ntp*2+half], ah[mt], ql+half*2);
            }
        }
    }

#pragma unroll
    for(int mt=0;mt<2;++mt)
#pragma unroll
    for(int nt=0;nt<8;++nt){
        int lr0=wm*32+mt*16+(lane>>2);
        int col=n0 + wn*64 + nt*8 + (lane&3)*2;
#pragma unroll
        for(int h2=0;h2<2;++h2){
            int lr=lr0+h2*8;
            if(m0+lr<cnt){
                float2 v; v.x=acc[mt][nt][h2*2]; v.y=acc[mt][nt][h2*2+1];
                *(float2*)(g_y+(size_t)(slot0+lr)*H_DIM+col)=v;
            }
        }
    }
}

// ---------------- 6) combine: out[t] = w0*y[slot0] + w1*y[slot1] -------------
__global__ void combine_kernel(float* __restrict__ Out, int T){
    int idx=blockIdx.x*blockDim.x+threadIdx.x;
    int total=T*(H_DIM/4);
    if(idx>=total) return;
    int t=idx/(H_DIM/4), q=idx%(H_DIM/4);
    unsigned s0=g_slotinfo[2*t], s1=g_slotinfo[2*t+1];
    float w0=g_top_w[2*t], w1=g_top_w[2*t+1];
    int sl0=g_off[s0>>13]+(int)(s0&8191);
    int sl1=g_off[s1>>13]+(int)(s1&8191);
    float4 a=*(const float4*)(g_y+(size_t)sl0*H_DIM+q*4);
    float4 b=*(const float4*)(g_y+(size_t)sl1*H_DIM+q*4);
    float4 o;
    o.x=w0*a.x+w1*b.x; o.y=w0*a.y+w1*b.y;
    o.z=w0*a.z+w1*b.z; o.w=w0*a.w+w1*b.w;
    *(float4*)(Out+(size_t)t*H_DIM+q*4)=o;
}

// ---------------- launch ------------------------------------------------------
extern "C" void kernel_launch(void* const* d_in, const int* in_sizes, int n_in,
                              void* d_out, int out_size){
    const float* x =(const float*)d_in[0];
    const float* gw=(const float*)d_in[1];
    const float* w1=(const float*)d_in[2];
    const float* w3=(const float*)d_in[3];
    const float* w2=(const float*)d_in[4];
    float* out=(float*)d_out;
    const int T=in_sizes[0]/H_DIM;

    cudaFuncSetAttribute(moe_gemm1_mma, cudaFuncAttributeMaxDynamicSharedMemorySize, G1_SMEM);
    cudaFuncSetAttribute(moe_gemm2_mma, cudaFuncAttributeMaxDynamicSharedMemorySize, G2_SMEM);

    router_kernel<<<(T+7)/8,256>>>(x,gw,T);
    build_lists_kernel<<<E_NUM,256>>>(T);
    prep_kernel<<<49152,dim3(32,8)>>>(w1,w3,w2);
    const int mt=(T+127)/128;
    moe_gemm1_mma<<<dim3(I_DIM/64,  mt, E_NUM),256,G1_SMEM>>>();
    moe_gemm2_mma<<<dim3(H_DIM/128, mt, E_NUM),256,G2_SMEM>>>();
    combine_kernel<<<(T*(H_DIM/4)+255)/256,256>>>(out,T);
}